// round 2
// baseline (speedup 1.0000x reference)
#include <cuda_runtime.h>

#define DIMN   1024
#define NHEADS 16
#define HDIM   64
#define NBATCH 2
#define SEQL   2048
#define MTOT   (NBATCH*SEQL)   // 4096

// Scratch for projected q/k/v, laid out [b, s, h, d] == [m, n] with n = h*64+d
__device__ float g_q[(size_t)MTOT * DIMN];
__device__ float g_k[(size_t)MTOT * DIMN];
__device__ float g_v[(size_t)MTOT * DIMN];

typedef unsigned long long u64;

__device__ __forceinline__ u64 pack2(float lo, float hi) {
    u64 r;
    asm("mov.b64 %0, {%1, %2};" : "=l"(r)
        : "r"(__float_as_uint(lo)), "r"(__float_as_uint(hi)));
    return r;
}
__device__ __forceinline__ void unpack2(u64 v, float& lo, float& hi) {
    unsigned int a, b;
    asm("mov.b64 {%0, %1}, %2;" : "=r"(a), "=r"(b) : "l"(v));
    lo = __uint_as_float(a);
    hi = __uint_as_float(b);
}
__device__ __forceinline__ u64 fma2(u64 a, u64 b, u64 c) {
    u64 d;
    asm("fma.rn.f32x2 %0, %1, %2, %3;" : "=l"(d) : "l"(a), "l"(b), "l"(c));
    return d;
}
__device__ __forceinline__ u64 mul2(u64 a, u64 b) {
    u64 d;
    asm("mul.rn.f32x2 %0, %1, %2;" : "=l"(d) : "l"(a), "l"(b));
    return d;
}

// ============================================================================
// QKV projection: Y[m][n] = sum_k X[m][k] * W[n][k] + bias[n]
// 128x128 CTA tile, BK=16, 256 threads, 8x8 microtile, f32x2 packed FMA.
// grid = (DIMN/128, MTOT/128, 3); z selects (Wq,bq,g_q)/(Wk,..)/(Wv,..)
// ============================================================================
#define BM 128
#define BN 128
#define BK 16

__global__ void __launch_bounds__(256, 2) qkv_gemm_kernel(
    const float* __restrict__ X,
    const float* __restrict__ Wq, const float* __restrict__ bq,
    const float* __restrict__ Wk, const float* __restrict__ bk,
    const float* __restrict__ Wv, const float* __restrict__ bv)
{
    const float* W;
    const float* bias;
    float* Y;
    if (blockIdx.z == 0)      { W = Wq; bias = bq; Y = g_q; }
    else if (blockIdx.z == 1) { W = Wk; bias = bk; Y = g_k; }
    else                      { W = Wv; bias = bv; Y = g_v; }

    __shared__ float As[BK * BM];   // As[k][m]
    __shared__ float Bs[BK * BN];   // Bs[k][n]

    const int t  = threadIdx.x;
    const int ty = t >> 4;          // 0..15 -> M microtile row group
    const int tx = t & 15;          // 0..15 -> N microtile col group
    const int m0 = blockIdx.y * BM;
    const int n0 = blockIdx.x * BN;

    u64 acc[8][4] = {};             // 8 rows x 8 cols as 4 f32x2 pairs

    for (int k0 = 0; k0 < DIMN; k0 += BK) {
        // ---- load A (X tile) and B (W tile), transposed into smem ----
        #pragma unroll
        for (int it = 0; it < 2; it++) {
            int f   = t + it * 256;          // 0..511 float4 slots
            int row = f >> 2;                // 0..127
            int kc  = (f & 3) * 4;           // 0,4,8,12
            float4 xa = *(const float4*)&X[(size_t)(m0 + row) * DIMN + k0 + kc];
            As[(kc + 0) * BM + row] = xa.x;
            As[(kc + 1) * BM + row] = xa.y;
            As[(kc + 2) * BM + row] = xa.z;
            As[(kc + 3) * BM + row] = xa.w;
            float4 wb = *(const float4*)&W[(size_t)(n0 + row) * DIMN + k0 + kc];
            Bs[(kc + 0) * BN + row] = wb.x;
            Bs[(kc + 1) * BN + row] = wb.y;
            Bs[(kc + 2) * BN + row] = wb.z;
            Bs[(kc + 3) * BN + row] = wb.w;
        }
        __syncthreads();

        // ---- compute ----
        #pragma unroll
        for (int kk = 0; kk < BK; kk++) {
            float4 a0 = *(const float4*)&As[kk * BM + ty * 8];
            float4 a1 = *(const float4*)&As[kk * BM + ty * 8 + 4];
            float aF[8] = {a0.x, a0.y, a0.z, a0.w, a1.x, a1.y, a1.z, a1.w};
            u64 b2[4];
            #pragma unroll
            for (int j = 0; j < 4; j++)
                b2[j] = *(const u64*)&Bs[kk * BN + tx * 8 + 2 * j];
            #pragma unroll
            for (int i = 0; i < 8; i++) {
                u64 aa = pack2(aF[i], aF[i]);
                #pragma unroll
                for (int j = 0; j < 4; j++)
                    acc[i][j] = fma2(aa, b2[j], acc[i][j]);
            }
        }
        __syncthreads();
    }

    // ---- epilogue: add bias, store ----
    float bF[8];
    #pragma unroll
    for (int j = 0; j < 8; j++) bF[j] = bias[n0 + tx * 8 + j];

    #pragma unroll
    for (int i = 0; i < 8; i++) {
        size_t mrow = (size_t)(m0 + ty * 8 + i) * DIMN;
        #pragma unroll
        for (int j = 0; j < 4; j++) {
            float lo, hi;
            unpack2(acc[i][j], lo, hi);
            float2 o;
            o.x = lo + bF[2 * j];
            o.y = hi + bF[2 * j + 1];
            *(float2*)&Y[mrow + n0 + tx * 8 + 2 * j] = o;
        }
    }
}

// ============================================================================
// Flash attention, fp32. CTA = 64 queries of one (batch, head).
// smem: Qs[d][q] (prescaled), KP: K phase [d][kc] / P phase [kc][q], Vs[kc][d].
// Exactly 48 KB static smem. 256 threads: (ty,tx) owns 4 q-rows x 4 cols.
// ============================================================================
#define QT 64
#define KT 64

__global__ void __launch_bounds__(256) attn_kernel(float* __restrict__ Out)
{
    __shared__ float Qs[QT * HDIM];   // Qs[d*64 + q]
    __shared__ float KP[KT * HDIM];   // Ks[d*64 + kc]  then  Ps[kc*64 + q]
    __shared__ float Vs[KT * HDIM];   // Vs[kc*64 + d]

    const int t  = threadIdx.x;
    const int ty = t >> 4;            // 0..15: q rows ty*4..ty*4+3
    const int tx = t & 15;            // 0..15: cols tx*4..tx*4+3
    const int s0 = blockIdx.x * QT;
    const int bh = blockIdx.y;
    const int b  = bh >> 4;
    const int h  = bh & 15;

    const float scale = 0.125f;       // 1/sqrt(64)

    // ---- load Q tile, transposed, pre-scaled ----
    #pragma unroll
    for (int it = 0; it < 4; it++) {
        int f = t + it * 256;          // 0..1023
        int r = f >> 4;                // q row 0..63
        int c = (f & 15) * 4;          // d
        size_t gbase = (((size_t)(b * SEQL + s0 + r)) * NHEADS + h) * HDIM + c;
        float4 v = *(const float4*)&g_q[gbase];
        Qs[(c + 0) * 64 + r] = v.x * scale;
        Qs[(c + 1) * 64 + r] = v.y * scale;
        Qs[(c + 2) * 64 + r] = v.z * scale;
        Qs[(c + 3) * 64 + r] = v.w * scale;
    }

    float m_i[4], l_i[4];
    u64 o2[4][2] = {};
    #pragma unroll
    for (int i = 0; i < 4; i++) { m_i[i] = -1e30f; l_i[i] = 0.0f; }

    for (int kt = 0; kt < SEQL / KT; kt++) {
        __syncthreads();   // prev-iter PV reads done (and Qs writes at kt=0)

        // ---- load K (transposed) and V (natural) ----
        #pragma unroll
        for (int it = 0; it < 4; it++) {
            int f = t + it * 256;
            int r = f >> 4;
            int c = (f & 15) * 4;
            size_t gbase = (((size_t)(b * SEQL + kt * KT + r)) * NHEADS + h) * HDIM + c;
            float4 kv = *(const float4*)&g_k[gbase];
            KP[(c + 0) * 64 + r] = kv.x;
            KP[(c + 1) * 64 + r] = kv.y;
            KP[(c + 2) * 64 + r] = kv.z;
            KP[(c + 3) * 64 + r] = kv.w;
            float4 vv = *(const float4*)&g_v[gbase];
            *(float4*)&Vs[r * 64 + c] = vv;
        }
        __syncthreads();

        // ---- S = (Q*scale) . K^T : s2[i][j2] pairs over key cols ----
        u64 s2[4][2] = {};
        #pragma unroll
        for (int d = 0; d < HDIM; d++) {
            float4 a4 = *(const float4*)&Qs[d * 64 + ty * 4];
            u64 k20 = *(const u64*)&KP[d * 64 + tx * 4];
            u64 k21 = *(const u64*)&KP[d * 64 + tx * 4 + 2];
            float aF[4] = {a4.x, a4.y, a4.z, a4.w};
            #pragma unroll
            for (int i = 0; i < 4; i++) {
                u64 aa = pack2(aF[i], aF[i]);
                s2[i][0] = fma2(aa, k20, s2[i][0]);
                s2[i][1] = fma2(aa, k21, s2[i][1]);
            }
        }

        float s[4][4];
        #pragma unroll
        for (int i = 0; i < 4; i++) {
            unpack2(s2[i][0], s[i][0], s[i][1]);
            unpack2(s2[i][1], s[i][2], s[i][3]);
        }

        __syncthreads();   // all K reads done before P overwrites KP

        // ---- online softmax (row stats replicated across the 16 tx lanes) ----
        #pragma unroll
        for (int i = 0; i < 4; i++) {
            float tmax = fmaxf(fmaxf(s[i][0], s[i][1]), fmaxf(s[i][2], s[i][3]));
            #pragma unroll
            for (int off = 8; off >= 1; off >>= 1)
                tmax = fmaxf(tmax, __shfl_xor_sync(0xffffffffu, tmax, off, 16));
            float newm = fmaxf(m_i[i], tmax);
            float corr = __expf(m_i[i] - newm);
            m_i[i] = newm;
            float rsum = 0.0f;
            #pragma unroll
            for (int j = 0; j < 4; j++) {
                float p = __expf(s[i][j] - newm);
                s[i][j] = p;
                rsum += p;
            }
            #pragma unroll
            for (int off = 8; off >= 1; off >>= 1)
                rsum += __shfl_xor_sync(0xffffffffu, rsum, off, 16);
            l_i[i] = l_i[i] * corr + rsum;
            u64 c2 = pack2(corr, corr);
            o2[i][0] = mul2(o2[i][0], c2);
            o2[i][1] = mul2(o2[i][1], c2);
        }

        // ---- write P transposed: Ps[kc][q] ----
        #pragma unroll
        for (int i = 0; i < 4; i++)
            #pragma unroll
            for (int j = 0; j < 4; j++)
                KP[(tx * 4 + j) * 64 + ty * 4 + i] = s[i][j];
        __syncthreads();

        // ---- O += P . V ----
        #pragma unroll
        for (int kc = 0; kc < KT; kc++) {
            float4 p4 = *(const float4*)&KP[kc * 64 + ty * 4];
            u64 v20 = *(const u64*)&Vs[kc * 64 + tx * 4];
            u64 v21 = *(const u64*)&Vs[kc * 64 + tx * 4 + 2];
            float pF[4] = {p4.x, p4.y, p4.z, p4.w};
            #pragma unroll
            for (int i = 0; i < 4; i++) {
                u64 pp = pack2(pF[i], pF[i]);
                o2[i][0] = fma2(pp, v20, o2[i][0]);
                o2[i][1] = fma2(pp, v21, o2[i][1]);
            }
        }
    }

    // ---- normalize and store ----
    #pragma unroll
    for (int i = 0; i < 4; i++) {
        float inv = 1.0f / l_i[i];
        size_t gbase = (((size_t)(b * SEQL + s0 + ty * 4 + i)) * NHEADS + h) * HDIM + tx * 4;
        float lo, hi;
        unpack2(o2[i][0], lo, hi);
        float2 o;
        o.x = lo * inv; o.y = hi * inv;
        *(float2*)&Out[gbase] = o;
        unpack2(o2[i][1], lo, hi);
        o.x = lo * inv; o.y = hi * inv;
        *(float2*)&Out[gbase + 2] = o;
    }
}

// ============================================================================
// Launch
// ============================================================================
extern "C" void kernel_launch(void* const* d_in, const int* in_sizes, int n_in,
                              void* d_out, int out_size)
{
    const float* x  = (const float*)d_in[0];
    const float* Wq = (const float*)d_in[1];
    const float* bq = (const float*)d_in[2];
    const float* Wk = (const float*)d_in[3];
    const float* bk = (const float*)d_in[4];
    const float* Wv = (const float*)d_in[5];
    const float* bv = (const float*)d_in[6];
    float* out = (float*)d_out;

    dim3 gg(DIMN / BN, MTOT / BM, 3);      // (8, 32, 3)
    qkv_gemm_kernel<<<gg, 256>>>(x, Wq, bq, Wk, bk, Wv, bv);

    dim3 ga(SEQL / QT, NBATCH * NHEADS);   // (32, 32)
    attn_kernel<<<ga, 256>>>(out);
}